// round 9
// baseline (speedup 1.0000x reference)
#include <cuda_runtime.h>

constexpr int Nn = 4096;   // z rows
constexpr int Mm = 1024;   // e rows
constexpr int Dd = 64;     // feature dim

constexpr int NH  = 2048;                    // z-half per build block
constexpr int BK  = 2048;                    // buckets per half-column
constexpr float LOb  = -6.0f;
constexpr float HIb  =  6.0f;
constexpr float INVW = BK / (HIb - LOb);

__device__ __forceinline__ int bucket_of(float v) {
    int k = (int)((v - LOb) * INVW);
    return min(max(k, 0), BK - 1);
}

// Scratch (no allocations allowed -> device globals)
__device__ __align__(16) float g_zt[Dd * Nn];    // z transposed: [D][N]
__device__ __align__(16) float g_et[Dd * Mm];    // e transposed: [D][M]
__device__ float g_pb0[Dd * Mm];                 // per-query best, z-half 0
__device__ float g_pb1[Dd * Mm];                 // per-query best, z-half 1
__device__ int   g_ctr;                          // k2 completion counter (0 at rest)

// ---------------------------------------------------------------------------
// k1: fused transpose(z) + mask + copy; first 64 blocks also transpose e.
// Grid (2, 128), block (32,32) -> 256 blocks = single wave.
__global__ void k1_prep(const float* __restrict__ z, const float* __restrict__ e,
                        const int* __restrict__ idx, float* __restrict__ out) {
    __shared__ float tile[32][33];
    int bx = blockIdx.x, by = blockIdx.y;
    int tx = threadIdx.x, ty = threadIdx.y;

    // ---- z tile ----
    int x = bx * 32 + tx;                // D index
    int y = by * 32 + ty;                // N index
    float v = z[y * Dd + x];
    tile[ty][tx] = v;

    int k = idx[y];
    out[1 + y * Dd + x]           = (x < k) ? v : 0.0f;   // z_masked
    out[1 + Nn * Dd + y * Dd + x] = v;                    // z_copy

    __syncthreads();
    int ox = by * 32 + tx;               // N index (output inner)
    int oy = bx * 32 + ty;               // D index (output outer)
    g_zt[oy * Nn + ox] = tile[tx][ty];

    // ---- e tile (first 32 by-rows x 2 bx-cols cover all of e) ----
    if (by < 32) {
        __syncthreads();                 // tile reuse
        int m = by * 32 + ty;            // M index
        tile[ty][tx] = e[m * Dd + x];
        __syncthreads();
        int om = by * 32 + tx;           // M index (output inner)
        int od = bx * 32 + ty;           // D index (output outer)
        g_et[od * Mm + om] = tile[tx][ty];
    }
}

// ---------------------------------------------------------------------------
// k2: grid 128 = 64 columns x 2 z-halves. Block (d,h) buckets its half of
// column d (2048 values), queries all 1024 e's against it, stores per-query
// best into g_pb{0,1} (disjoint -> plain stores). Last block to finish
// reduces both arrays into out[0] and resets the counter.
__global__ void __launch_bounds__(1024, 1) k2_nn(float* __restrict__ out) {
    __shared__ float S[NH];          // bucket-grouped half-column (8 KB)
    __shared__ int   cnt[BK];        // hist -> exclusive starts (8 KB)
    __shared__ int   wtot[32];
    __shared__ int   is_last;
    __shared__ float red[32];

    const int bx = blockIdx.x;       // 0..127
    const int d  = bx & 63;
    const int h  = bx >> 6;          // which z-half
    const int t  = threadIdx.x;
    const int lane = t & 31, wid = t >> 5;

    // Prefetch query + z values (coalesced; overlap the build).
    float x  = g_et[d * Mm + t];
    float v0 = g_zt[d * Nn + h * NH + t];
    float v1 = g_zt[d * Nn + h * NH + t + 1024];

    cnt[t] = 0; cnt[t + 1024] = 0;
    __syncthreads();

    // ---- single atomic pass: histogram + within-bucket rank ----
    int b0 = bucket_of(v0), b1 = bucket_of(v1);
    int r0 = atomicAdd(&cnt[b0], 1);
    int r1 = atomicAdd(&cnt[b1], 1);
    __syncthreads();

    // ---- block exclusive scan (2 buckets per thread) ----
    int c0 = cnt[2 * t], c1 = cnt[2 * t + 1];
    int s = c0 + c1;
    int inc = s;
    #pragma unroll
    for (int o = 1; o < 32; o <<= 1) {
        int n = __shfl_up_sync(0xFFFFFFFFu, inc, o);
        if (lane >= o) inc += n;
    }
    if (lane == 31) wtot[wid] = inc;
    __syncthreads();
    if (wid == 0) {
        int ws = wtot[lane];
        int wi = ws;
        #pragma unroll
        for (int o = 1; o < 32; o <<= 1) {
            int n = __shfl_up_sync(0xFFFFFFFFu, wi, o);
            if (lane >= o) wi += n;
        }
        wtot[lane] = wi - ws;            // exclusive warp offsets
    }
    __syncthreads();
    int excl = (inc - s) + wtot[wid];
    cnt[2 * t]     = excl;
    cnt[2 * t + 1] = excl + c0;
    __syncthreads();

    // ---- scatter: plain stores (start + rank is unique) ----
    S[cnt[b0] + r0] = v0;
    S[cnt[b1] + r1] = v1;
    __syncthreads();

    // ---- query: own bucket + nearest nonempty bucket each side ----
    int k0 = bucket_of(x);
    int start = cnt[k0];
    int end   = (k0 < BK - 1) ? cnt[k0 + 1] : NH;

    float best = 1e30f;
    for (int j = start; j < end; j++)
        best = fminf(best, fabsf(S[j] - x));

    if (start > 0) {                     // nearest nonempty bucket below
        float bv = S[start - 1];
        int b = bucket_of(bv);
        int lo = cnt[b];
        for (int j = lo; j < start; j++)
            best = fminf(best, fabsf(S[j] - x));
    }
    if (end < NH) {                      // nearest nonempty bucket above
        float av = S[end];
        int b = bucket_of(av);
        int hi = (b < BK - 1) ? cnt[b + 1] : NH;
        for (int j = end; j < hi; j++)
            best = fminf(best, fabsf(S[j] - x));
    }

    // Disjoint plain stores (halves write different arrays).
    if (h == 0) g_pb0[d * Mm + t] = best;
    else        g_pb1[d * Mm + t] = best;

    // ---- last-block reduction ----
    __syncthreads();
    if (t == 0) {
        __threadfence();                             // publish stores
        int old = atomicAdd(&g_ctr, 1);
        is_last = (old == 127);
    }
    __syncthreads();
    if (!is_last) return;

    // All 128 blocks' stores are L2-visible. Read with L2-scope loads.
    float val = 0.0f;
    #pragma unroll
    for (int i = 0; i < (Dd * Mm) / 1024; i++) {
        int j = i * 1024 + t;
        float a = __ldcg(&g_pb0[j]);
        float b = __ldcg(&g_pb1[j]);
        float m = fminf(a, b);
        val += m * m;
    }
    val *= (1.0f / (float)(Mm * Dd));
    #pragma unroll
    for (int o = 16; o > 0; o >>= 1)
        val += __shfl_xor_sync(0xFFFFFFFFu, val, o);
    if (lane == 0) red[wid] = val;
    __syncthreads();
    if (wid == 0) {
        float sv = red[lane];
        #pragma unroll
        for (int o = 16; o > 0; o >>= 1)
            sv += __shfl_xor_sync(0xFFFFFFFFu, sv, o);
        if (lane == 0) {
            out[0] = sv;
            g_ctr = 0;                   // reset for next graph replay
        }
    }
}

// ---------------------------------------------------------------------------
extern "C" void kernel_launch(void* const* d_in, const int* in_sizes, int n_in,
                              void* d_out, int out_size) {
    const float* z = (const float*)d_in[0];
    const float* e = (const float*)d_in[1];
    const int* idx = (const int*)d_in[2];
    float* out = (float*)d_out;

    k1_prep<<<dim3(2, 128), dim3(32, 32)>>>(z, e, idx, out);
    k2_nn<<<128, 1024>>>(out);
}

// round 10
// speedup vs baseline: 1.1727x; 1.1727x over previous
#include <cuda_runtime.h>

constexpr int Nn = 4096;   // z rows
constexpr int Mm = 1024;   // e rows
constexpr int Dd = 64;     // feature dim

constexpr int NH  = 2048;                    // z-half per build block
constexpr int BK  = 2048;                    // buckets per half-column
constexpr float LOb  = -6.0f;
constexpr float HIb  =  6.0f;
constexpr float INVW = BK / (HIb - LOb);

__device__ __forceinline__ int bucket_of(float v) {
    int k = (int)((v - LOb) * INVW);
    return min(max(k, 0), BK - 1);
}
// Order-preserving float<->uint key map (unsigned compare == float compare).
__device__ __forceinline__ unsigned map_key(float v) {
    unsigned u = __float_as_uint(v);
    return (u & 0x80000000u) ? ~u : (u | 0x80000000u);
}
__device__ __forceinline__ float unmap_key(unsigned k) {
    return __uint_as_float((k & 0x80000000u) ? (k & 0x7FFFFFFFu) : ~k);
}

// Scratch (no allocations allowed -> device globals)
__device__ __align__(16) float g_zt[Dd * Nn];    // z transposed: [D][N]
__device__ __align__(16) float g_et[Dd * Mm];    // e transposed: [D][M]
__device__ float g_pb0[Dd * Mm];                 // per-query best, z-half 0
__device__ float g_pb1[Dd * Mm];                 // per-query best, z-half 1

// ---------------------------------------------------------------------------
// k1: fused transpose(z) + mask + copy (+ e transpose in first 64 blocks).
// Grid (2, 128), block (32,32) -> 256 blocks = single wave.
__global__ void k1_prep(const float* __restrict__ z, const float* __restrict__ e,
                        const int* __restrict__ idx, float* __restrict__ out) {
    __shared__ float tile[32][33];
    int bx = blockIdx.x, by = blockIdx.y;
    int tx = threadIdx.x, ty = threadIdx.y;

    // ---- z tile ----
    int x = bx * 32 + tx;                // D index
    int y = by * 32 + ty;                // N index
    float v = z[y * Dd + x];
    tile[ty][tx] = v;

    int k = idx[y];
    out[1 + y * Dd + x]           = (x < k) ? v : 0.0f;   // z_masked
    out[1 + Nn * Dd + y * Dd + x] = v;                    // z_copy
    if (bx == 0 && by == 0 && tx == 0 && ty == 0) out[0] = 0.0f;

    __syncthreads();
    int ox = by * 32 + tx;               // N index (output inner)
    int oy = bx * 32 + ty;               // D index (output outer)
    g_zt[oy * Nn + ox] = tile[tx][ty];

    // ---- e tile (by<32 x bx in {0,1} covers all of e) ----
    if (by < 32) {
        __syncthreads();                 // tile reuse
        int m = by * 32 + ty;            // M index
        tile[ty][tx] = e[m * Dd + x];
        __syncthreads();
        int om = by * 32 + tx;           // M index (output inner)
        int od = bx * 32 + ty;           // D index (output outer)
        g_et[od * Mm + om] = tile[tx][ty];
    }
}

// ---------------------------------------------------------------------------
// k2: grid 128 = 64 columns x 2 z-halves. Block (d,h) buckets its half of
// column d (2048 values) and records per-bucket min/max (key-mapped). Query:
// scan own bucket, then neighbor contributions via bmax[prev] / bmin[next]
// (each bucket's extremum dominates all its members for an outside query).
// Per-query best -> disjoint plain stores (no init, no atomics).
__global__ void __launch_bounds__(1024, 1) k2_nn() {
    __shared__ float    S[NH];       // bucket-grouped half-column (8 KB)
    __shared__ int      cnt[BK];     // hist -> exclusive starts (8 KB)
    __shared__ unsigned kmax[BK];    // per-bucket max key (8 KB)
    __shared__ unsigned kmin[BK];    // per-bucket min key (8 KB)
    __shared__ int      wtot[32];

    const int bx = blockIdx.x;       // 0..127
    const int d  = bx & 63;
    const int h  = bx >> 6;          // which z-half
    const int t  = threadIdx.x;
    const int lane = t & 31, wid = t >> 5;

    // Prefetch query + z values (coalesced; overlap the build).
    float x  = g_et[d * Mm + t];
    float v0 = g_zt[d * Nn + h * NH + t];
    float v1 = g_zt[d * Nn + h * NH + t + 1024];

    cnt[t] = 0;            cnt[t + 1024] = 0;
    kmax[t] = 0u;          kmax[t + 1024] = 0u;
    kmin[t] = 0xFFFFFFFFu; kmin[t + 1024] = 0xFFFFFFFFu;
    __syncthreads();

    // ---- single atomic pass: histogram + rank + per-bucket min/max ----
    int b0 = bucket_of(v0), b1 = bucket_of(v1);
    int r0 = atomicAdd(&cnt[b0], 1);
    int r1 = atomicAdd(&cnt[b1], 1);
    unsigned key0 = map_key(v0), key1 = map_key(v1);
    atomicMax(&kmax[b0], key0);  atomicMin(&kmin[b0], key0);
    atomicMax(&kmax[b1], key1);  atomicMin(&kmin[b1], key1);
    __syncthreads();

    // ---- block exclusive scan (2 buckets per thread) ----
    int c0 = cnt[2 * t], c1 = cnt[2 * t + 1];
    int s = c0 + c1;
    int inc = s;
    #pragma unroll
    for (int o = 1; o < 32; o <<= 1) {
        int n = __shfl_up_sync(0xFFFFFFFFu, inc, o);
        if (lane >= o) inc += n;
    }
    if (lane == 31) wtot[wid] = inc;
    __syncthreads();
    if (wid == 0) {
        int ws = wtot[lane];
        int wi = ws;
        #pragma unroll
        for (int o = 1; o < 32; o <<= 1) {
            int n = __shfl_up_sync(0xFFFFFFFFu, wi, o);
            if (lane >= o) wi += n;
        }
        wtot[lane] = wi - ws;            // exclusive warp offsets
    }
    __syncthreads();
    int excl = (inc - s) + wtot[wid];
    cnt[2 * t]     = excl;
    cnt[2 * t + 1] = excl + c0;
    __syncthreads();

    // ---- scatter: plain stores (start + rank is unique) ----
    S[cnt[b0] + r0] = v0;
    S[cnt[b1] + r1] = v1;
    __syncthreads();

    // ---- query ----
    int k0 = bucket_of(x);
    int start = cnt[k0];
    int end   = (k0 < BK - 1) ? cnt[k0 + 1] : NH;

    float best = 1e30f;
    for (int j = start; j < end; j++)          // own bucket (values straddle x)
        best = fminf(best, fabsf(S[j] - x));

    if (start > 0) {                           // nearest nonempty bucket below
        int b = bucket_of(S[start - 1]);       // id via boundary element
        best = fminf(best, x - unmap_key(kmax[b]));   // all its values < x
    }
    if (end < NH) {                            // nearest nonempty bucket above
        int b = bucket_of(S[end]);
        best = fminf(best, unmap_key(kmin[b]) - x);   // all its values > x
    }

    // Disjoint plain stores (halves write different arrays).
    if (h == 0) g_pb0[d * Mm + t] = best;
    else        g_pb1[d * Mm + t] = best;
}

// ---------------------------------------------------------------------------
// k3: combine halves + reduce -> out[0] += sum(min(a,b)^2) / 65536.
__global__ void k3_reduce(float* __restrict__ out) {
    __shared__ float red[32];
    int i = blockIdx.x * 1024 + threadIdx.x;
    float a = g_pb0[i];
    float b = g_pb1[i];
    float m = fminf(a, b);
    float val = m * m * (1.0f / (float)(Mm * Dd));
    const int lane = threadIdx.x & 31, wid = threadIdx.x >> 5;
    #pragma unroll
    for (int o = 16; o > 0; o >>= 1)
        val += __shfl_xor_sync(0xFFFFFFFFu, val, o);
    if (lane == 0) red[wid] = val;
    __syncthreads();
    if (wid == 0) {
        float sv = red[lane];
        #pragma unroll
        for (int o = 16; o > 0; o >>= 1)
            sv += __shfl_xor_sync(0xFFFFFFFFu, sv, o);
        if (lane == 0) atomicAdd(out, sv);
    }
}

// ---------------------------------------------------------------------------
extern "C" void kernel_launch(void* const* d_in, const int* in_sizes, int n_in,
                              void* d_out, int out_size) {
    const float* z = (const float*)d_in[0];
    const float* e = (const float*)d_in[1];
    const int* idx = (const int*)d_in[2];
    float* out = (float*)d_out;

    k1_prep<<<dim3(2, 128), dim3(32, 32)>>>(z, e, idx, out);
    k2_nn<<<128, 1024>>>();
    k3_reduce<<<64, 1024>>>(out);
}